// round 5
// baseline (speedup 1.0000x reference)
#include <cuda_runtime.h>

// Problem constants
#define TT   256   // timesteps
#define HH   256   // hidden
#define BB   512   // batch
#define NCTA 86    // CTAs
#define RR   6     // batch rows per CTA (86*6 = 516 >= 512, last CTA padded)

typedef unsigned long long u64;

// Preprocessed weights: k-major, gate-interleaved.
// g_W*[k*256 + j] = { W[(0*256+j)*256+k], W[(1*256+j)*256+k],
//                     W[(2*256+j)*256+k], W[(3*256+j)*256+k] }  (i,f,g,o)
__device__ float4 g_W1i[256 * 256];  // from W_hh1
__device__ float4 g_W2a[256 * 256];  // from W_ih2
__device__ float4 g_W2b[256 * 256];  // from W_hh2

__global__ void prep_kernel(const float* __restrict__ Whh1,
                            const float* __restrict__ Wih2,
                            const float* __restrict__ Whh2) {
    int idx = blockIdx.x * blockDim.x + threadIdx.x;  // 0 .. 256*256*4-1
    if (idx >= 256 * 256 * 4) return;
    int q = idx & 3;
    int j = (idx >> 2) & 255;
    int k = idx >> 10;
    int src = (q * 256 + j) * 256 + k;
    reinterpret_cast<float*>(g_W1i)[idx] = Whh1[src];
    reinterpret_cast<float*>(g_W2a)[idx] = Wih2[src];
    reinterpret_cast<float*>(g_W2b)[idx] = Whh2[src];
}

// ---- f32x2 packed helpers (Blackwell packed fp32: 2x FFMA throughput) ----
__device__ __forceinline__ u64 pack2(float lo, float hi) {
    u64 r;
    asm("mov.b64 %0, {%1, %2};" : "=l"(r) : "f"(lo), "f"(hi));
    return r;
}
__device__ __forceinline__ void unpack2(u64 v, float& lo, float& hi) {
    asm("mov.b64 {%0, %1}, %2;" : "=f"(lo), "=f"(hi) : "l"(v));
}
__device__ __forceinline__ u64 ffma2(u64 a, u64 b, u64 c) {
    u64 d;
    asm("fma.rn.f32x2 %0, %1, %2, %3;" : "=l"(d) : "l"(a), "l"(b), "l"(c));
    return d;
}

__device__ __forceinline__ float sigmf(float x) {
    return __fdividef(1.0f, 1.0f + __expf(-x));
}
__device__ __forceinline__ float tanhf_fast(float x) {
    // tanh(x) = 2*sigmoid(2x) - 1 ; safe at large |x| (exp->inf or ->0)
    return __fdividef(2.0f, 1.0f + __expf(-2.0f * x)) - 1.0f;
}

// LSTM pointwise on a pair of batch rows packed in f32x2 accumulators.
__device__ __forceinline__ u64 cell_pair(u64 gi, u64 gf, u64 gg, u64 go,
                                         float& ca, float& cb) {
    float i0, i1, f0, f1, g0, g1, o0, o1;
    unpack2(gi, i0, i1);
    unpack2(gf, f0, f1);
    unpack2(gg, g0, g1);
    unpack2(go, o0, o1);
    ca = sigmf(f0) * ca + sigmf(i0) * tanhf_fast(g0);
    cb = sigmf(f1) * cb + sigmf(i1) * tanhf_fast(g1);
    float h0 = sigmf(o0) * tanhf_fast(ca);
    float h1 = sigmf(o1) * tanhf_fast(cb);
    return pack2(h0, h1);
}

__global__ void __launch_bounds__(256) lstm_kernel(
    const float* __restrict__ x_in,   // (512,256,2)
    const float* __restrict__ W_ih1,  // (1024,2)
    const float* __restrict__ b_ih1, const float* __restrict__ b_hh1,
    const float* __restrict__ b_ih2, const float* __restrict__ b_hh2,
    const float* __restrict__ W_lin,  // (2,256)
    const float* __restrict__ b_lin,  // (2,)
    float* __restrict__ out)          // (512,256,2)
{
    // h-state as f32x2 row pairs: sh*[p*256 + k] holds (h[2p][k], h[2p+1][k])
    __shared__ u64 sh1[3 * 256];
    __shared__ u64 sh2[3 * 256];
    __shared__ float sh_x[RR][2];
    __shared__ float sh_wl[2][256];

    const int j   = threadIdx.x;   // hidden unit owned by this thread
    const int b0  = blockIdx.x * RR;
    const int lane = j & 31;
    const int warp = j >> 5;

    // Per-thread constants (hidden unit j owns gate rows j, 256+j, 512+j, 768+j)
    float bias1[4], bias2[4], wx0[4], wx1[4];
#pragma unroll
    for (int q = 0; q < 4; q++) {
        int row = q * 256 + j;
        bias1[q] = b_ih1[row] + b_hh1[row];
        bias2[q] = b_ih2[row] + b_hh2[row];
        wx0[q] = W_ih1[row * 2 + 0];
        wx1[q] = W_ih1[row * 2 + 1];
    }
    sh_wl[0][j] = W_lin[j];
    sh_wl[1][j] = W_lin[256 + j];

    // zero initial state
    sh1[j] = 0ULL; sh1[256 + j] = 0ULL; sh1[512 + j] = 0ULL;
    sh2[j] = 0ULL; sh2[256 + j] = 0ULL; sh2[512 + j] = 0ULL;
    float c1[RR], c2[RR];
#pragma unroll
    for (int r = 0; r < RR; r++) { c1[r] = 0.0f; c2[r] = 0.0f; }

    const float blin0 = b_lin[0], blin1 = b_lin[1];

    for (int t = 0; t < TT; t++) {
        // stage x_t for this CTA's rows (pad rows read as 0)
        if (j < RR * 2) {
            int r = j >> 1, c = j & 1;
            int b = b0 + r;
            sh_x[r][c] = (b < BB) ? x_in[(b * TT + t) * 2 + c] : 0.0f;
        }
        __syncthreads();

        u64 acc[4][3];

        // ===== layer 1: gates = bias1 + x*Wih1^T + h1*Whh1^T =====
#pragma unroll
        for (int q = 0; q < 4; q++) {
            float g[RR];
#pragma unroll
            for (int r = 0; r < RR; r++)
                g[r] = fmaf(sh_x[r][1], wx1[q], fmaf(sh_x[r][0], wx0[q], bias1[q]));
#pragma unroll
            for (int p = 0; p < 3; p++) acc[q][p] = pack2(g[2 * p], g[2 * p + 1]);
        }
        {
            const float4* __restrict__ wp = g_W1i + j;
#pragma unroll 8
            for (int k = 0; k < 256; k++) {
                float4 w = __ldg(wp + k * 256);
                u64 h0 = sh1[k];
                u64 h1 = sh1[256 + k];
                u64 h2 = sh1[512 + k];
#pragma unroll
                for (int q = 0; q < 4; q++) {
                    float wv = (&w.x)[q];
                    u64 wq = pack2(wv, wv);
                    acc[q][0] = ffma2(wq, h0, acc[q][0]);
                    acc[q][1] = ffma2(wq, h1, acc[q][1]);
                    acc[q][2] = ffma2(wq, h2, acc[q][2]);
                }
            }
        }
        __syncthreads();  // all reads of sh1 (h1 prev) done
#pragma unroll
        for (int p = 0; p < 3; p++)
            sh1[p * 256 + j] = cell_pair(acc[0][p], acc[1][p], acc[2][p], acc[3][p],
                                         c1[2 * p], c1[2 * p + 1]);
        __syncthreads();  // h1 new visible

        // ===== layer 2: gates = bias2 + h1*Wih2^T + h2*Whh2^T =====
#pragma unroll
        for (int q = 0; q < 4; q++) {
            u64 bq = pack2(bias2[q], bias2[q]);
            acc[q][0] = bq; acc[q][1] = bq; acc[q][2] = bq;
        }
        {
            const float4* __restrict__ wpa = g_W2a + j;
            const float4* __restrict__ wpb = g_W2b + j;
#pragma unroll 4
            for (int k = 0; k < 256; k++) {
                float4 wa = __ldg(wpa + k * 256);
                float4 wb = __ldg(wpb + k * 256);
                u64 a0 = sh1[k], a1 = sh1[256 + k], a2 = sh1[512 + k];
                u64 e0 = sh2[k], e1 = sh2[256 + k], e2 = sh2[512 + k];
#pragma unroll
                for (int q = 0; q < 4; q++) {
                    float wva = (&wa.x)[q];
                    u64 wqa = pack2(wva, wva);
                    acc[q][0] = ffma2(wqa, a0, acc[q][0]);
                    acc[q][1] = ffma2(wqa, a1, acc[q][1]);
                    acc[q][2] = ffma2(wqa, a2, acc[q][2]);
                    float wvb = (&wb.x)[q];
                    u64 wqb = pack2(wvb, wvb);
                    acc[q][0] = ffma2(wqb, e0, acc[q][0]);
                    acc[q][1] = ffma2(wqb, e1, acc[q][1]);
                    acc[q][2] = ffma2(wqb, e2, acc[q][2]);
                }
            }
        }
        __syncthreads();  // all reads of sh2 (h2 prev) done
#pragma unroll
        for (int p = 0; p < 3; p++)
            sh2[p * 256 + j] = cell_pair(acc[0][p], acc[1][p], acc[2][p], acc[3][p],
                                         c2[2 * p], c2[2 * p + 1]);
        __syncthreads();  // h2 new visible

        // ===== y = h2 * W_lin^T + b_lin : warp r handles batch row r =====
        if (warp < RR) {
            int r = warp;
            int b = b0 + r;
            if (b < BB) {
                int p = r >> 1, e = r & 1;
                const float* h2f = reinterpret_cast<const float*>(sh2 + p * 256);
                float s0 = 0.0f, s1 = 0.0f;
#pragma unroll
                for (int m = 0; m < 8; m++) {
                    int k = lane + m * 32;
                    float h = h2f[k * 2 + e];
                    s0 = fmaf(sh_wl[0][k], h, s0);
                    s1 = fmaf(sh_wl[1][k], h, s1);
                }
#pragma unroll
                for (int off = 16; off; off >>= 1) {
                    s0 += __shfl_xor_sync(0xffffffffu, s0, off);
                    s1 += __shfl_xor_sync(0xffffffffu, s1, off);
                }
                if (lane == 0) {
                    out[(b * TT + t) * 2 + 0] = s0 + blin0;
                    out[(b * TT + t) * 2 + 1] = s1 + blin1;
                }
            }
        }
        // next iteration's first __syncthreads orders sh_x/sh2 reuse
    }
}

extern "C" void kernel_launch(void* const* d_in, const int* in_sizes, int n_in,
                              void* d_out, int out_size) {
    const float* inputs = (const float*)d_in[0];
    const float* W_ih1  = (const float*)d_in[1];
    const float* W_hh1  = (const float*)d_in[2];
    const float* b_ih1  = (const float*)d_in[3];
    const float* b_hh1  = (const float*)d_in[4];
    const float* W_ih2  = (const float*)d_in[5];
    const float* W_hh2  = (const float*)d_in[6];
    const float* b_ih2  = (const float*)d_in[7];
    const float* b_hh2  = (const float*)d_in[8];
    const float* W_lin  = (const float*)d_in[9];
    const float* b_lin  = (const float*)d_in[10];

    prep_kernel<<<1024, 256>>>(W_hh1, W_ih2, W_hh2);
    lstm_kernel<<<NCTA, 256>>>(inputs, W_ih1, b_ih1, b_hh1, b_ih2, b_hh2,
                               W_lin, b_lin, (float*)d_out);
}

// round 6
// speedup vs baseline: 1.1585x; 1.1585x over previous
#include <cuda_runtime.h>

// Problem constants
#define TT   256   // timesteps
#define BB   512   // batch
#define NCTA 86    // CTAs (one per SM, 86*6 >= 512)
#define RR   6     // batch rows per CTA

typedef unsigned long long u64;

// Preprocessed weights, k-pair-major, gate-pair split:
//   g_W[(m*2 + qp)*256 + j] = float4{ W[g0][j][2m],   W[g1][j][2m],
//                                     W[g0][j][2m+1], W[g1][j][2m+1] }
// where g0 = 2*qp, g1 = 2*qp+1 and W[q][j][k] = orig[(q*256+j)*256 + k].
__device__ float4 g_W1 [256 * 256];  // from W_hh1
__device__ float4 g_W2a[256 * 256];  // from W_ih2
__device__ float4 g_W2b[256 * 256];  // from W_hh2

__global__ void prep_kernel(const float* __restrict__ Whh1,
                            const float* __restrict__ Wih2,
                            const float* __restrict__ Whh2) {
    int e = blockIdx.x * blockDim.x + threadIdx.x;  // float-element index
    if (e >= 256 * 256 * 4) return;
    int f  = e & 3;
    int j  = (e >> 2) & 255;
    int qp = (e >> 10) & 1;
    int m  = e >> 11;
    int kk = 2 * m + (f >> 1);
    int q  = 2 * qp + (f & 1);
    int src = (q * 256 + j) * 256 + kk;
    reinterpret_cast<float*>(g_W1)[e]  = Whh1[src];
    reinterpret_cast<float*>(g_W2a)[e] = Wih2[src];
    reinterpret_cast<float*>(g_W2b)[e] = Whh2[src];
}

// ---- f32x2 packed helpers ----
__device__ __forceinline__ u64 pack2(float lo, float hi) {
    u64 r;
    asm("mov.b64 %0, {%1, %2};" : "=l"(r) : "f"(lo), "f"(hi));
    return r;
}
__device__ __forceinline__ void unpack2(u64 v, float& lo, float& hi) {
    asm("mov.b64 {%0, %1}, %2;" : "=f"(lo), "=f"(hi) : "l"(v));
}
__device__ __forceinline__ u64 ffma2(u64 a, u64 b, u64 c) {
    u64 d;
    asm("fma.rn.f32x2 %0, %1, %2, %3;" : "=l"(d) : "l"(a), "l"(b), "l"(c));
    return d;
}

__device__ __forceinline__ float sigmf(float x) {
    return __fdividef(1.0f, 1.0f + __expf(-x));
}
__device__ __forceinline__ float tanhf_fast(float x) {
    return __fdividef(2.0f, 1.0f + __expf(-2.0f * x)) - 1.0f;
}

// LSTM pointwise on a pair of batch rows packed in f32x2 accumulators.
__device__ __forceinline__ u64 cell_pair(u64 gi, u64 gf, u64 gg, u64 go,
                                         float& ca, float& cb) {
    float i0, i1, f0, f1, g0, g1, o0, o1;
    unpack2(gi, i0, i1);
    unpack2(gf, f0, f1);
    unpack2(gg, g0, g1);
    unpack2(go, o0, o1);
    ca = sigmf(f0) * ca + sigmf(i0) * tanhf_fast(g0);
    cb = sigmf(f1) * cb + sigmf(i1) * tanhf_fast(g1);
    float h0 = sigmf(o0) * tanhf_fast(ca);
    float h1 = sigmf(o1) * tanhf_fast(cb);
    return pack2(h0, h1);
}

__global__ void __launch_bounds__(512) lstm_kernel(
    const float* __restrict__ x_in,   // (512,256,2)
    const float* __restrict__ W_ih1,  // (1024,2)
    const float* __restrict__ b_ih1, const float* __restrict__ b_hh1,
    const float* __restrict__ b_ih2, const float* __restrict__ b_hh2,
    const float* __restrict__ W_lin,  // (2,256)
    const float* __restrict__ b_lin,  // (2,)
    float* __restrict__ out)          // (512,256,2)
{
    // h-state: sh*[p*256 + k] = f32x2 (h[2p][k], h[2p+1][k])
    __shared__ __align__(16) u64 sh1[3 * 256];
    __shared__ __align__(16) u64 sh2[3 * 256];
    // exchange buffer: (p,j) -> { acc_gate_g , acc_gate_o } (two u64)
    __shared__ __align__(16) u64 exch[3 * 256 * 2];
    __shared__ float sh_x[RR][2];
    __shared__ float sh_wl[2][256];

    const int tid  = threadIdx.x;
    const int j    = tid & 255;     // hidden unit
    const int qp   = tid >> 8;      // 0: gates i,f   1: gates g,o
    const int b0   = blockIdx.x * RR;
    const int lane = tid & 31;
    const int warp = tid >> 5;

    // Per-thread constants for this thread's two gates (q = 2qp, 2qp+1)
    float bias1[2], bias2[2], wx0[2], wx1[2];
#pragma unroll
    for (int g = 0; g < 2; g++) {
        int row = (2 * qp + g) * 256 + j;
        bias1[g] = b_ih1[row] + b_hh1[row];
        bias2[g] = b_ih2[row] + b_hh2[row];
        wx0[g] = W_ih1[row * 2 + 0];
        wx1[g] = W_ih1[row * 2 + 1];
    }
    if (qp == 0) {
        sh_wl[0][j] = W_lin[j];
        sh_wl[1][j] = W_lin[256 + j];
    }
    for (int i = tid; i < 3 * 256; i += 512) { sh1[i] = 0ULL; sh2[i] = 0ULL; }

    float c1[RR], c2[RR];
#pragma unroll
    for (int r = 0; r < RR; r++) { c1[r] = 0.0f; c2[r] = 0.0f; }

    const float blin0 = b_lin[0], blin1 = b_lin[1];

    const u64 bias2p0 = pack2(bias2[0], bias2[0]);
    const u64 bias2p1 = pack2(bias2[1], bias2[1]);

    for (int t = 0; t < TT; t++) {
        // stage x_t (prior readers finished before the last sync of step t-1)
        if (tid < RR * 2) {
            int r = tid >> 1, c = tid & 1;
            int b = b0 + r;
            sh_x[r][c] = (b < BB) ? x_in[(b * TT + t) * 2 + c] : 0.0f;
        }
        __syncthreads();  // x visible; sh1/sh2/exch safe to consume

        u64 acc[2][3];

        // ===== layer 1: gates = bias + x*Wih1^T + h1*Whh1^T =====
#pragma unroll
        for (int g = 0; g < 2; g++) {
            float gr[RR];
#pragma unroll
            for (int r = 0; r < RR; r++)
                gr[r] = fmaf(sh_x[r][1], wx1[g], fmaf(sh_x[r][0], wx0[g], bias1[g]));
#pragma unroll
            for (int p = 0; p < 3; p++) acc[g][p] = pack2(gr[2 * p], gr[2 * p + 1]);
        }
        {
            const float4* __restrict__ wp = g_W1 + qp * 256 + j;
#pragma unroll 4
            for (int m = 0; m < 128; m++) {
                float4 w = __ldg(wp); wp += 512;
                ulonglong2 H0 = *reinterpret_cast<const ulonglong2*>(&sh1[0 * 256 + 2 * m]);
                ulonglong2 H1 = *reinterpret_cast<const ulonglong2*>(&sh1[1 * 256 + 2 * m]);
                ulonglong2 H2 = *reinterpret_cast<const ulonglong2*>(&sh1[2 * 256 + 2 * m]);
                u64 wq;
                wq = pack2(w.x, w.x);
                acc[0][0] = ffma2(wq, H0.x, acc[0][0]);
                acc[0][1] = ffma2(wq, H1.x, acc[0][1]);
                acc[0][2] = ffma2(wq, H2.x, acc[0][2]);
                wq = pack2(w.y, w.y);
                acc[1][0] = ffma2(wq, H0.x, acc[1][0]);
                acc[1][1] = ffma2(wq, H1.x, acc[1][1]);
                acc[1][2] = ffma2(wq, H2.x, acc[1][2]);
                wq = pack2(w.z, w.z);
                acc[0][0] = ffma2(wq, H0.y, acc[0][0]);
                acc[0][1] = ffma2(wq, H1.y, acc[0][1]);
                acc[0][2] = ffma2(wq, H2.y, acc[0][2]);
                wq = pack2(w.w, w.w);
                acc[1][0] = ffma2(wq, H0.y, acc[1][0]);
                acc[1][1] = ffma2(wq, H1.y, acc[1][1]);
                acc[1][2] = ffma2(wq, H2.y, acc[1][2]);
            }
        }
        if (qp == 1) {
#pragma unroll
            for (int p = 0; p < 3; p++)
                *reinterpret_cast<ulonglong2*>(&exch[(p * 256 + j) * 2]) =
                    make_ulonglong2(acc[0][p], acc[1][p]);   // (g, o)
        }
        __syncthreads();  // exch full; all sh1 reads done
        if (qp == 0) {
#pragma unroll
            for (int p = 0; p < 3; p++) {
                ulonglong2 go = *reinterpret_cast<const ulonglong2*>(&exch[(p * 256 + j) * 2]);
                sh1[p * 256 + j] = cell_pair(acc[0][p], acc[1][p], go.x, go.y,
                                             c1[2 * p], c1[2 * p + 1]);
            }
        }
        __syncthreads();  // new h1 visible; exch free

        // ===== layer 2: gates = bias + h1*Wih2^T + h2*Whh2^T =====
        acc[0][0] = bias2p0; acc[0][1] = bias2p0; acc[0][2] = bias2p0;
        acc[1][0] = bias2p1; acc[1][1] = bias2p1; acc[1][2] = bias2p1;
        {
            const float4* __restrict__ wp = g_W2a + qp * 256 + j;
#pragma unroll 4
            for (int m = 0; m < 128; m++) {
                float4 w = __ldg(wp); wp += 512;
                ulonglong2 H0 = *reinterpret_cast<const ulonglong2*>(&sh1[0 * 256 + 2 * m]);
                ulonglong2 H1 = *reinterpret_cast<const ulonglong2*>(&sh1[1 * 256 + 2 * m]);
                ulonglong2 H2 = *reinterpret_cast<const ulonglong2*>(&sh1[2 * 256 + 2 * m]);
                u64 wq;
                wq = pack2(w.x, w.x);
                acc[0][0] = ffma2(wq, H0.x, acc[0][0]);
                acc[0][1] = ffma2(wq, H1.x, acc[0][1]);
                acc[0][2] = ffma2(wq, H2.x, acc[0][2]);
                wq = pack2(w.y, w.y);
                acc[1][0] = ffma2(wq, H0.x, acc[1][0]);
                acc[1][1] = ffma2(wq, H1.x, acc[1][1]);
                acc[1][2] = ffma2(wq, H2.x, acc[1][2]);
                wq = pack2(w.z, w.z);
                acc[0][0] = ffma2(wq, H0.y, acc[0][0]);
                acc[0][1] = ffma2(wq, H1.y, acc[0][1]);
                acc[0][2] = ffma2(wq, H2.y, acc[0][2]);
                wq = pack2(w.w, w.w);
                acc[1][0] = ffma2(wq, H0.y, acc[1][0]);
                acc[1][1] = ffma2(wq, H1.y, acc[1][1]);
                acc[1][2] = ffma2(wq, H2.y, acc[1][2]);
            }
        }
        {
            const float4* __restrict__ wp = g_W2b + qp * 256 + j;
#pragma unroll 4
            for (int m = 0; m < 128; m++) {
                float4 w = __ldg(wp); wp += 512;
                ulonglong2 H0 = *reinterpret_cast<const ulonglong2*>(&sh2[0 * 256 + 2 * m]);
                ulonglong2 H1 = *reinterpret_cast<const ulonglong2*>(&sh2[1 * 256 + 2 * m]);
                ulonglong2 H2 = *reinterpret_cast<const ulonglong2*>(&sh2[2 * 256 + 2 * m]);
                u64 wq;
                wq = pack2(w.x, w.x);
                acc[0][0] = ffma2(wq, H0.x, acc[0][0]);
                acc[0][1] = ffma2(wq, H1.x, acc[0][1]);
                acc[0][2] = ffma2(wq, H2.x, acc[0][2]);
                wq = pack2(w.y, w.y);
                acc[1][0] = ffma2(wq, H0.x, acc[1][0]);
                acc[1][1] = ffma2(wq, H1.x, acc[1][1]);
                acc[1][2] = ffma2(wq, H2.x, acc[1][2]);
                wq = pack2(w.z, w.z);
                acc[0][0] = ffma2(wq, H0.y, acc[0][0]);
                acc[0][1] = ffma2(wq, H1.y, acc[0][1]);
                acc[0][2] = ffma2(wq, H2.y, acc[0][2]);
                wq = pack2(w.w, w.w);
                acc[1][0] = ffma2(wq, H0.y, acc[1][0]);
                acc[1][1] = ffma2(wq, H1.y, acc[1][1]);
                acc[1][2] = ffma2(wq, H2.y, acc[1][2]);
            }
        }
        if (qp == 1) {
#pragma unroll
            for (int p = 0; p < 3; p++)
                *reinterpret_cast<ulonglong2*>(&exch[(p * 256 + j) * 2]) =
                    make_ulonglong2(acc[0][p], acc[1][p]);
        }
        __syncthreads();  // exch full; all sh1/sh2 reads done
        if (qp == 0) {
#pragma unroll
            for (int p = 0; p < 3; p++) {
                ulonglong2 go = *reinterpret_cast<const ulonglong2*>(&exch[(p * 256 + j) * 2]);
                sh2[p * 256 + j] = cell_pair(acc[0][p], acc[1][p], go.x, go.y,
                                             c2[2 * p], c2[2 * p + 1]);
            }
        }
        __syncthreads();  // new h2 visible

        // ===== y = h2 * W_lin^T + b_lin : warp r handles batch row r =====
        if (warp < RR) {
            int r = warp;
            int b = b0 + r;
            if (b < BB) {
                int p = r >> 1, e = r & 1;
                const float* h2f = reinterpret_cast<const float*>(sh2 + p * 256);
                float s0 = 0.0f, s1 = 0.0f;
#pragma unroll
                for (int mm = 0; mm < 8; mm++) {
                    int k = lane + mm * 32;
                    float h = h2f[k * 2 + e];
                    s0 = fmaf(sh_wl[0][k], h, s0);
                    s1 = fmaf(sh_wl[1][k], h, s1);
                }
#pragma unroll
                for (int off = 16; off; off >>= 1) {
                    s0 += __shfl_xor_sync(0xffffffffu, s0, off);
                    s1 += __shfl_xor_sync(0xffffffffu, s1, off);
                }
                if (lane == 0) {
                    out[(b * TT + t) * 2 + 0] = s0 + blin0;
                    out[(b * TT + t) * 2 + 1] = s1 + blin1;
                }
            }
        }
        // next iteration's first __syncthreads orders sh_x / buffer reuse
    }
}

extern "C" void kernel_launch(void* const* d_in, const int* in_sizes, int n_in,
                              void* d_out, int out_size) {
    const float* inputs = (const float*)d_in[0];
    const float* W_ih1  = (const float*)d_in[1];
    const float* W_hh1  = (const float*)d_in[2];
    const float* b_ih1  = (const float*)d_in[3];
    const float* b_hh1  = (const float*)d_in[4];
    const float* W_ih2  = (const float*)d_in[5];
    const float* W_hh2  = (const float*)d_in[6];
    const float* b_ih2  = (const float*)d_in[7];
    const float* b_hh2  = (const float*)d_in[8];
    const float* W_lin  = (const float*)d_in[9];
    const float* b_lin  = (const float*)d_in[10];

    prep_kernel<<<1024, 256>>>(W_hh1, W_ih2, W_hh2);
    lstm_kernel<<<NCTA, 512>>>(inputs, W_ih1, b_ih1, b_hh1, b_ih2, b_hh2,
                               W_lin, b_lin, (float*)d_out);
}

// round 7
// speedup vs baseline: 1.3655x; 1.1787x over previous
#include <cuda_runtime.h>

#define TT   256   // timesteps
#define BB   512   // batch
#define NCTA 86    // CTAs (one per SM; 86*6 >= 512)
#define RR   6     // batch rows per CTA

typedef unsigned long long u64;

// Weight layout (per matrix), float4 index:
//   idx4 = (m*2 + qp)*512 + j*2 + ks      m in [0,64), qp in [0,2), j in [0,256), ks in [0,2)
// float element f of that float4 is W_orig[(q*256+j)*256 + k] with
//   q = 2*qp + (f&1),  k = ks*128 + 2*m + (f>>1)
// i.e. float4 = ( Wg0[k0], Wg1[k0], Wg0[k1], Wg1[k1] ), k0 = ks*128+2m, k1 = k0+1.
__device__ float4 g_W1 [256 * 256];  // from W_hh1
__device__ float4 g_W2a[256 * 256];  // from W_ih2
__device__ float4 g_W2b[256 * 256];  // from W_hh2

__global__ void prep_kernel(const float* __restrict__ Whh1,
                            const float* __restrict__ Wih2,
                            const float* __restrict__ Whh2) {
    int e = blockIdx.x * blockDim.x + threadIdx.x;
    if (e >= 256 * 256 * 4) return;
    int f    = e & 3;
    int idx4 = e >> 2;
    int ks   = idx4 & 1;
    int j    = (idx4 >> 1) & 255;
    int qp   = (idx4 >> 9) & 1;
    int m    = idx4 >> 10;
    int q    = 2 * qp + (f & 1);
    int k    = ks * 128 + 2 * m + (f >> 1);
    int src  = (q * 256 + j) * 256 + k;
    reinterpret_cast<float*>(g_W1)[e]  = Whh1[src];
    reinterpret_cast<float*>(g_W2a)[e] = Wih2[src];
    reinterpret_cast<float*>(g_W2b)[e] = Whh2[src];
}

// ---- f32x2 packed helpers ----
__device__ __forceinline__ u64 pack2(float lo, float hi) {
    u64 r;
    asm("mov.b64 %0, {%1, %2};" : "=l"(r) : "f"(lo), "f"(hi));
    return r;
}
__device__ __forceinline__ void unpack2(u64 v, float& lo, float& hi) {
    asm("mov.b64 {%0, %1}, %2;" : "=f"(lo), "=f"(hi) : "l"(v));
}
__device__ __forceinline__ u64 ffma2(u64 a, u64 b, u64 c) {
    u64 d;
    asm("fma.rn.f32x2 %0, %1, %2, %3;" : "=l"(d) : "l"(a), "l"(b), "l"(c));
    return d;
}

__device__ __forceinline__ float sigmf(float x) {
    return __fdividef(1.0f, 1.0f + __expf(-x));
}
__device__ __forceinline__ float tanhf_fast(float x) {
    return __fdividef(2.0f, 1.0f + __expf(-2.0f * x)) - 1.0f;
}

// cross-k-half reduction: lanes ks=0/1 are adjacent (lane bit 0)
__device__ __forceinline__ u64 red2(u64 v) {
    float lo, hi;
    unpack2(v, lo, hi);
    float lo2 = __shfl_xor_sync(0xffffffffu, lo, 1);
    float hi2 = __shfl_xor_sync(0xffffffffu, hi, 1);
    return pack2(lo + lo2, hi + hi2);
}

// LSTM pointwise on a pair of batch rows packed in f32x2.
__device__ __forceinline__ u64 cell_pair(u64 gi, u64 gf, u64 gg, u64 go,
                                         float& ca, float& cb) {
    float i0, i1, f0, f1, g0, g1, o0, o1;
    unpack2(gi, i0, i1);
    unpack2(gf, f0, f1);
    unpack2(gg, g0, g1);
    unpack2(go, o0, o1);
    ca = sigmf(f0) * ca + sigmf(i0) * tanhf_fast(g0);
    cb = sigmf(f1) * cb + sigmf(i1) * tanhf_fast(g1);
    float h0 = sigmf(o0) * tanhf_fast(ca);
    float h1 = sigmf(o1) * tanhf_fast(cb);
    return pack2(h0, h1);
}

// h smem index for hidden unit k, row-pair p (+16B skew between k-halves)
#define HIDX(k, p) ((k) * 3 + (p) + (((k) >> 7) << 1))
#define HSZ 772

// one m-step of a matvec: w float4 + 6 packed-h values -> 12 ffma2
__device__ __forceinline__ void mm_step(const float4* __restrict__ wp,
                                        const u64* __restrict__ hb,
                                        int m, u64 acc[2][3]) {
    float4 w = __ldg(wp);
    ulonglong2 Ha = *reinterpret_cast<const ulonglong2*>(hb + 6 * m);
    ulonglong2 Hb = *reinterpret_cast<const ulonglong2*>(hb + 6 * m + 2);
    ulonglong2 Hc = *reinterpret_cast<const ulonglong2*>(hb + 6 * m + 4);
    u64 wq;
    wq = pack2(w.x, w.x);   // gate g0, k0
    acc[0][0] = ffma2(wq, Ha.x, acc[0][0]);
    acc[0][1] = ffma2(wq, Ha.y, acc[0][1]);
    acc[0][2] = ffma2(wq, Hb.x, acc[0][2]);
    wq = pack2(w.y, w.y);   // gate g1, k0
    acc[1][0] = ffma2(wq, Ha.x, acc[1][0]);
    acc[1][1] = ffma2(wq, Ha.y, acc[1][1]);
    acc[1][2] = ffma2(wq, Hb.x, acc[1][2]);
    wq = pack2(w.z, w.z);   // gate g0, k1
    acc[0][0] = ffma2(wq, Hb.y, acc[0][0]);
    acc[0][1] = ffma2(wq, Hc.x, acc[0][1]);
    acc[0][2] = ffma2(wq, Hc.y, acc[0][2]);
    wq = pack2(w.w, w.w);   // gate g1, k1
    acc[1][0] = ffma2(wq, Hb.y, acc[1][0]);
    acc[1][1] = ffma2(wq, Hc.x, acc[1][1]);
    acc[1][2] = ffma2(wq, Hc.y, acc[1][2]);
}

__global__ void __launch_bounds__(1024) lstm_kernel(
    const float* __restrict__ x_in,   // (512,256,2)
    const float* __restrict__ W_ih1,  // (1024,2)
    const float* __restrict__ b_ih1, const float* __restrict__ b_hh1,
    const float* __restrict__ b_ih2, const float* __restrict__ b_hh2,
    const float* __restrict__ W_lin,  // (2,256)
    const float* __restrict__ b_lin,  // (2,)
    float* __restrict__ out)          // (512,256,2)
{
    // h-state, k-major: sh*[HIDX(k,p)] = f32x2 (h[2p][k], h[2p+1][k])
    __shared__ __align__(16) u64 sh1[HSZ];
    __shared__ __align__(16) u64 sh2[HSZ];
    // exchange: (j,p) -> { acc_gate_g , acc_gate_o }
    __shared__ __align__(16) u64 exch[256 * 3 * 2];
    __shared__ float sh_x[RR][2];
    __shared__ float sh_wl[2][256];

    const int tid  = threadIdx.x;
    const int ks   = tid & 1;          // k-half
    const int j    = (tid >> 1) & 255; // hidden unit
    const int qp   = tid >> 9;         // 0: gates i,f   1: gates g,o
    const int b0   = blockIdx.x * RR;
    const int lane = tid & 31;
    const int warp = tid >> 5;

    // per-thread gate constants (gates 2qp, 2qp+1 of unit j)
    float bias1[2], bias2[2], wx0[2], wx1[2];
#pragma unroll
    for (int g = 0; g < 2; g++) {
        int row = (2 * qp + g) * 256 + j;
        bias1[g] = b_ih1[row] + b_hh1[row];
        bias2[g] = b_ih2[row] + b_hh2[row];
        wx0[g] = W_ih1[row * 2 + 0];
        wx1[g] = W_ih1[row * 2 + 1];
    }
    if (qp == 0 && ks == 0) {
        sh_wl[0][j] = W_lin[j];
        sh_wl[1][j] = W_lin[256 + j];
    }
    for (int i = tid; i < HSZ; i += 1024) { sh1[i] = 0ULL; sh2[i] = 0ULL; }

    float c1[4], c2[4];   // ks0: pairs 0,1 (4 vals); ks1: pair 2 (2 vals)
#pragma unroll
    for (int r = 0; r < 4; r++) { c1[r] = 0.0f; c2[r] = 0.0f; }

    const float blin0 = b_lin[0], blin1 = b_lin[1];

    const int woff = qp * 512 + j * 2 + ks;      // float4 offset within m-block
    const u64* hb1 = sh1 + ks * 386;             // this k-half's base in sh1
    const u64* hb2 = sh2 + ks * 386;

    for (int t = 0; t < TT; t++) {
        if (tid < RR * 2) {
            int r = tid >> 1, c = tid & 1;
            int b = b0 + r;
            sh_x[r][c] = (b < BB) ? x_in[(b * TT + t) * 2 + c] : 0.0f;
        }
        __syncthreads();  // x visible; all prev-step buffer reads complete

        u64 acc[2][3];

        // ===== layer 1 =====
        if (ks == 0) {  // bias + x-term only once (ks1 contributes pure partials)
#pragma unroll
            for (int g = 0; g < 2; g++) {
                float gr[RR];
#pragma unroll
                for (int r = 0; r < RR; r++)
                    gr[r] = fmaf(sh_x[r][1], wx1[g], fmaf(sh_x[r][0], wx0[g], bias1[g]));
#pragma unroll
                for (int p = 0; p < 3; p++) acc[g][p] = pack2(gr[2 * p], gr[2 * p + 1]);
            }
        } else {
#pragma unroll
            for (int g = 0; g < 2; g++)
#pragma unroll
                for (int p = 0; p < 3; p++) acc[g][p] = 0ULL;
        }
        {
            const float4* __restrict__ wp = g_W1 + woff;
#pragma unroll 4
            for (int m = 0; m < 64; m++, wp += 1024) mm_step(wp, hb1, m, acc);
        }
#pragma unroll
        for (int g = 0; g < 2; g++)
#pragma unroll
            for (int p = 0; p < 3; p++) acc[g][p] = red2(acc[g][p]);

        if (qp == 1) {  // publish (g,o); ks0 -> pairs 0,1 ; ks1 -> pair 2
            if (ks == 0) {
                *reinterpret_cast<ulonglong2*>(&exch[(j * 3 + 0) * 2]) =
                    make_ulonglong2(acc[0][0], acc[1][0]);
                *reinterpret_cast<ulonglong2*>(&exch[(j * 3 + 1) * 2]) =
                    make_ulonglong2(acc[0][1], acc[1][1]);
            } else {
                *reinterpret_cast<ulonglong2*>(&exch[(j * 3 + 2) * 2]) =
                    make_ulonglong2(acc[0][2], acc[1][2]);
            }
        }
        __syncthreads();  // exch full; all sh1 reads done
        if (qp == 0) {
            if (ks == 0) {
#pragma unroll
                for (int p = 0; p < 2; p++) {
                    ulonglong2 go = *reinterpret_cast<const ulonglong2*>(&exch[(j * 3 + p) * 2]);
                    sh1[HIDX(j, p)] = cell_pair(acc[0][p], acc[1][p], go.x, go.y,
                                                c1[2 * p], c1[2 * p + 1]);
                }
            } else {
                ulonglong2 go = *reinterpret_cast<const ulonglong2*>(&exch[(j * 3 + 2) * 2]);
                sh1[HIDX(j, 2)] = cell_pair(acc[0][2], acc[1][2], go.x, go.y,
                                            c1[0], c1[1]);
            }
        }
        __syncthreads();  // new h1 visible; exch free

        // ===== layer 2 =====
        if (ks == 0) {
            u64 b0p = pack2(bias2[0], bias2[0]);
            u64 b1p = pack2(bias2[1], bias2[1]);
            acc[0][0] = b0p; acc[0][1] = b0p; acc[0][2] = b0p;
            acc[1][0] = b1p; acc[1][1] = b1p; acc[1][2] = b1p;
        } else {
#pragma unroll
            for (int g = 0; g < 2; g++)
#pragma unroll
                for (int p = 0; p < 3; p++) acc[g][p] = 0ULL;
        }
        {
            const float4* __restrict__ wpa = g_W2a + woff;
            const float4* __restrict__ wpb = g_W2b + woff;
#pragma unroll 2
            for (int m = 0; m < 64; m++, wpa += 1024, wpb += 1024) {
                mm_step(wpa, hb1, m, acc);
                mm_step(wpb, hb2, m, acc);
            }
        }
#pragma unroll
        for (int g = 0; g < 2; g++)
#pragma unroll
            for (int p = 0; p < 3; p++) acc[g][p] = red2(acc[g][p]);

        if (qp == 1) {
            if (ks == 0) {
                *reinterpret_cast<ulonglong2*>(&exch[(j * 3 + 0) * 2]) =
                    make_ulonglong2(acc[0][0], acc[1][0]);
                *reinterpret_cast<ulonglong2*>(&exch[(j * 3 + 1) * 2]) =
                    make_ulonglong2(acc[0][1], acc[1][1]);
            } else {
                *reinterpret_cast<ulonglong2*>(&exch[(j * 3 + 2) * 2]) =
                    make_ulonglong2(acc[0][2], acc[1][2]);
            }
        }
        __syncthreads();  // exch full; sh1/sh2 reads done
        if (qp == 0) {
            if (ks == 0) {
#pragma unroll
                for (int p = 0; p < 2; p++) {
                    ulonglong2 go = *reinterpret_cast<const ulonglong2*>(&exch[(j * 3 + p) * 2]);
                    sh2[HIDX(j, p)] = cell_pair(acc[0][p], acc[1][p], go.x, go.y,
                                                c2[2 * p], c2[2 * p + 1]);
                }
            } else {
                ulonglong2 go = *reinterpret_cast<const ulonglong2*>(&exch[(j * 3 + 2) * 2]);
                sh2[HIDX(j, 2)] = cell_pair(acc[0][2], acc[1][2], go.x, go.y,
                                            c2[0], c2[1]);
            }
        }
        __syncthreads();  // new h2 visible

        // ===== y = h2 * W_lin^T + b_lin : warp r -> batch row r =====
        if (warp < RR) {
            int r = warp;
            int b = b0 + r;
            if (b < BB) {
                int p = r >> 1, e = r & 1;
                const float* f2 = reinterpret_cast<const float*>(sh2);
                float s0 = 0.0f, s1 = 0.0f;
#pragma unroll
                for (int mm = 0; mm < 8; mm++) {
                    int k = lane + mm * 32;
                    float h = f2[2 * HIDX(k, p) + e];
                    s0 = fmaf(sh_wl[0][k], h, s0);
                    s1 = fmaf(sh_wl[1][k], h, s1);
                }
#pragma unroll
                for (int off = 16; off; off >>= 1) {
                    s0 += __shfl_xor_sync(0xffffffffu, s0, off);
                    s1 += __shfl_xor_sync(0xffffffffu, s1, off);
                }
                if (lane == 0) {
                    out[(b * TT + t) * 2 + 0] = s0 + blin0;
                    out[(b * TT + t) * 2 + 1] = s1 + blin1;
                }
            }
        }
        // next iteration's first __syncthreads orders buffer reuse
    }
}

extern "C" void kernel_launch(void* const* d_in, const int* in_sizes, int n_in,
                              void* d_out, int out_size) {
    const float* inputs = (const float*)d_in[0];
    const float* W_ih1  = (const float*)d_in[1];
    const float* W_hh1  = (const float*)d_in[2];
    const float* b_ih1  = (const float*)d_in[3];
    const float* b_hh1  = (const float*)d_in[4];
    const float* W_ih2  = (const float*)d_in[5];
    const float* W_hh2  = (const float*)d_in[6];
    const float* b_ih2  = (const float*)d_in[7];
    const float* b_hh2  = (const float*)d_in[8];
    const float* W_lin  = (const float*)d_in[9];
    const float* b_lin  = (const float*)d_in[10];

    prep_kernel<<<1024, 256>>>(W_hh1, W_ih2, W_hh2);
    lstm_kernel<<<NCTA, 1024>>>(inputs, W_ih1, b_ih1, b_hh1, b_ih2, b_hh2,
                                W_lin, b_lin, (float*)d_out);
}